// round 3
// baseline (speedup 1.0000x reference)
#include <cuda_runtime.h>
#include <cuda_bf16.h>

// Problem constants
#define BB     4
#define NN     4096
#define FIN    256
#define FO     128
#define JT     32          // j-tile width in k_main
#define PSTRIDE 36         // PS row stride (conflict-free A-frag loads: bank = 4*gid+tig)
#define WHSTRIDE 136       // WhS row stride (conflict-free B-frag loads: bank = 8*tig+gid)

// Scratch (static device arrays: allocation-free rule)
__device__ float    g_Wh[BB * NN * FO];     // 8 MB
__device__ float    g_src[BB * NN];
__device__ float    g_dst[BB * NN];
__device__ unsigned g_dmax[BB];             // order-preserving encoded float max

// ---------------- order-preserving float<->uint encode ----------------
__device__ __forceinline__ unsigned encode_f(float f) {
    unsigned u = __float_as_uint(f);
    return (u & 0x80000000u) ? ~u : (u | 0x80000000u);
}
__device__ __forceinline__ float decode_key(unsigned k) {
    unsigned u = (k & 0x80000000u) ? (k ^ 0x80000000u) : ~k;
    return __uint_as_float(u);
}

// ---------------- kernel 0: init dmax ----------------
__global__ void k_init() {
    if (threadIdx.x < BB) g_dmax[threadIdx.x] = 0u;  // 0u <= every encoded key
}

// ---------------- kernel 1: Wh = h @ W^T + b (fp32 SGEMM) ----------------
// M=16384, N=128, K=256. BM=128, BN=128, BK=16. 256 threads, 8x8 per thread.
__global__ __launch_bounds__(256, 1) void k_wh(const float* __restrict__ h,
                                               const float* __restrict__ Ww,
                                               const float* __restrict__ Wb) {
    __shared__ __align__(16) float As[16][132];   // [k][m]
    __shared__ __align__(16) float Bs[16][132];   // [k][n]
    const int t  = threadIdx.x;
    const int tx = t & 15;          // n dir
    const int ty = t >> 4;          // m dir
    const int m0 = blockIdx.x * 128;

    float acc[8][8];
#pragma unroll
    for (int i = 0; i < 8; i++)
#pragma unroll
        for (int j = 0; j < 8; j++) acc[i][j] = 0.f;

    for (int k0 = 0; k0 < FIN; k0 += 16) {
        // stage A: h[m0+row][k0+c] -> As[c][row]
#pragma unroll
        for (int q = 0; q < 8; q++) {
            int idx = q * 256 + t;
            int row = idx >> 4, c = idx & 15;
            As[c][row] = h[(size_t)(m0 + row) * FIN + k0 + c];
        }
        // stage B: Ww[n][k0+c] -> Bs[c][n]
#pragma unroll
        for (int q = 0; q < 8; q++) {
            int idx = q * 256 + t;
            int n = idx >> 4, c = idx & 15;
            Bs[c][n] = Ww[n * FIN + k0 + c];
        }
        __syncthreads();
#pragma unroll
        for (int k = 0; k < 16; k++) {
            float4 a0 = *(const float4*)&As[k][ty * 8];
            float4 a1 = *(const float4*)&As[k][ty * 8 + 4];
            float4 b0 = *(const float4*)&Bs[k][tx * 8];
            float4 b1 = *(const float4*)&Bs[k][tx * 8 + 4];
            float a[8] = {a0.x, a0.y, a0.z, a0.w, a1.x, a1.y, a1.z, a1.w};
            float b[8] = {b0.x, b0.y, b0.z, b0.w, b1.x, b1.y, b1.z, b1.w};
#pragma unroll
            for (int i = 0; i < 8; i++)
#pragma unroll
                for (int j = 0; j < 8; j++) acc[i][j] = fmaf(a[i], b[j], acc[i][j]);
        }
        __syncthreads();
    }

    float wb[8];
#pragma unroll
    for (int j = 0; j < 8; j++) wb[j] = Wb[tx * 8 + j];
#pragma unroll
    for (int i = 0; i < 8; i++) {
        float* dst = &g_Wh[(size_t)(m0 + ty * 8 + i) * FO + tx * 8];
        float4 v0 = {acc[i][0] + wb[0], acc[i][1] + wb[1], acc[i][2] + wb[2], acc[i][3] + wb[3]};
        float4 v1 = {acc[i][4] + wb[4], acc[i][5] + wb[5], acc[i][6] + wb[6], acc[i][7] + wb[7]};
        *(float4*)dst       = v0;
        *(float4*)(dst + 4) = v1;
    }
}

// ---------------- kernel 2: src/dst dots + per-batch dst max ----------------
// 256 CTAs x 256 threads; warp handles 8 rows (CTA = 64 rows, within one batch).
__global__ __launch_bounds__(256, 1) void k_srcdst(const float* __restrict__ aw) {
    const int t = threadIdx.x, w = t >> 5, lane = t & 31;
    const int mbase = blockIdx.x * 64 + w * 8;
    const int b = (blockIdx.x * 64) / NN;

    float as[4], ad[4];
#pragma unroll
    for (int q = 0; q < 4; q++) {
        as[q] = aw[lane + 32 * q];
        ad[q] = aw[FO + lane + 32 * q];
    }
    float dmax = -3.4e38f;
#pragma unroll
    for (int r = 0; r < 8; r++) {
        const int m = mbase + r;
        const float* row = &g_Wh[(size_t)m * FO];
        float s = 0.f, d = 0.f;
#pragma unroll
        for (int q = 0; q < 4; q++) {
            float v = row[lane + 32 * q];
            s = fmaf(v, as[q], s);
            d = fmaf(v, ad[q], d);
        }
#pragma unroll
        for (int o = 16; o; o >>= 1) {
            s += __shfl_xor_sync(0xffffffffu, s, o);
            d += __shfl_xor_sync(0xffffffffu, d, o);
        }
        if (lane == 0) { g_src[m] = s; g_dst[m] = d; }
        dmax = fmaxf(dmax, d);
    }
    if (lane == 0) atomicMax(&g_dmax[b], encode_f(dmax));
}

// ---------------- kernel 3: fused masked-softmax + PV (tf32 mma) ----------------
struct __align__(16) SmemMain {
    float dstS[NN];                 // 16 KB: full dst row for this batch
    float srcS[128];                // src + a_b for the 128 i-rows
    float mS[128];                  // subtract-max per row
    float lS[128];                  // softmax denominators (written once, end)
    float invS[128];
    int   adjS[2][128 * JT];        // 2 x 16 KB
    float WhS[2][JT * WHSTRIDE];    // 2 x 17 KB
    float PS[128 * PSTRIDE];        // 18 KB
};

__device__ __forceinline__ void cpasync16(void* s, const void* g) {
    unsigned saddr = (unsigned)__cvta_generic_to_shared(s);
    asm volatile("cp.async.cg.shared.global [%0], [%1], 16;\n" :: "r"(saddr), "l"(g));
}

__device__ __forceinline__ void mma_tf32(float c[4], const unsigned a[4],
                                         unsigned b0, unsigned b1) {
    asm volatile(
        "mma.sync.aligned.m16n8k8.row.col.f32.tf32.tf32.f32 "
        "{%0,%1,%2,%3}, {%4,%5,%6,%7}, {%8,%9}, {%0,%1,%2,%3};\n"
        : "+f"(c[0]), "+f"(c[1]), "+f"(c[2]), "+f"(c[3])
        : "r"(a[0]), "r"(a[1]), "r"(a[2]), "r"(a[3]), "r"(b0), "r"(b1));
}

__device__ __forceinline__ void issue_copies(SmemMain* sm, int buf,
                                             const int* __restrict__ adjbase,
                                             const float* __restrict__ whbase,
                                             int tile, int t) {
    const int* gadj = adjbase + (size_t)tile * JT;
#pragma unroll
    for (int q = 0; q < 4; q++) {
        int op = q * 256 + t;
        int row = op >> 3, seg = op & 7;          // 8 x 16B per 32-int row
        cpasync16(&sm->adjS[buf][row * JT + seg * 4],
                  gadj + (size_t)row * NN + seg * 4);
    }
    const float* gwh = whbase + (size_t)tile * JT * FO;
#pragma unroll
    for (int q = 0; q < 4; q++) {
        int op = q * 256 + t;
        int row = op >> 5, seg = op & 31;         // 32 x 16B per 128-float row
        cpasync16(&sm->WhS[buf][row * WHSTRIDE + seg * 4],
                  gwh + row * FO + seg * 4);
    }
}

__global__ __launch_bounds__(256, 1) void k_main(const int* __restrict__ adj,
                                                 const float* __restrict__ abp,
                                                 float* __restrict__ out) {
    extern __shared__ char smraw[];
    SmemMain* sm = (SmemMain*)smraw;

    const int t = threadIdx.x;
    const int w = t >> 5, lane = t & 31;
    const int gid = lane >> 2, tig = lane & 3;
    const int wm = w & 3;      // 4 m-blocks of 32 rows
    const int wn = w >> 2;     // 2 n-blocks of 64 cols
    const int b  = blockIdx.y;
    const int i0 = blockIdx.x * 128;
    const float ab = __ldg(abp);

    const int*   adjbase = adj + ((size_t)b * NN + i0) * NN;
    const float* whbase  = g_Wh + (size_t)b * NN * FO;

    // prefetch tile 0
    issue_copies(sm, 0, adjbase, whbase, 0, t);
    asm volatile("cp.async.commit_group;\n" ::: "memory");

    // prologue SMEM fills
    const float dmaxf = decode_key(g_dmax[b]);
#pragma unroll
    for (int q = 0; q < 16; q++)
        sm->dstS[q * 256 + t] = g_dst[(size_t)b * NN + q * 256 + t];
    if (t < 128) {
        float s = g_src[(size_t)b * NN + i0 + t] + ab;
        sm->srcS[t] = s;
        float e = s + dmaxf;
        sm->mS[t] = fmaxf(e, 0.01f * e);   // leaky of the per-row upper bound
    }
    __syncthreads();

    // per-warp constants across all tiles: rows k*8+w
    float src_r[16], m_r[16];
#pragma unroll
    for (int k = 0; k < 16; k++) {
        src_r[k] = sm->srcS[k * 8 + w];
        m_r[k]   = sm->mS[k * 8 + w];
    }
    float rs[16];                           // register-resident row sums
#pragma unroll
    for (int k = 0; k < 16; k++) rs[k] = 0.f;

    float acc[2][8][4];
#pragma unroll
    for (int mt = 0; mt < 2; mt++)
#pragma unroll
        for (int nt = 0; nt < 8; nt++)
#pragma unroll
            for (int c = 0; c < 4; c++) acc[mt][nt][c] = 0.f;

    const int NTILES = NN / JT;   // 128
    for (int tile = 0; tile < NTILES; tile++) {
        const int cur = tile & 1;
        asm volatile("cp.async.wait_group 0;\n" ::: "memory");
        __syncthreads();

        // ---- phase 1: P tile (row sums stay in registers) ----
        const int jb = tile * JT;
#pragma unroll
        for (int k = 0; k < 16; k++) {
            const int row = k * 8 + w;          // each (k,w) owns one distinct row
            const int a = sm->adjS[cur][row * JT + lane];
            float e = src_r[k] + sm->dstS[jb + lane];
            e = fmaxf(e, 0.01f * e);            // LeakyReLU
            float p = (a > 0) ? __expf(e - m_r[k]) : 0.f;
            sm->PS[row * PSTRIDE + lane] = p;
            rs[k] += p;
        }

        if (tile + 1 < NTILES) {
            issue_copies(sm, cur ^ 1, adjbase, whbase, tile + 1, t);
            asm volatile("cp.async.commit_group;\n" ::: "memory");
        }
        __syncthreads();

        // ---- phase 2: acc += P(tf32) @ Wh(tf32) ----
#pragma unroll
        for (int kk = 0; kk < 4; kk++) {
            unsigned Af[2][4];
#pragma unroll
            for (int mt = 0; mt < 2; mt++) {
                const int r  = wm * 32 + mt * 16 + gid;
                const int cA = kk * 8 + tig;
                Af[mt][0] = __float_as_uint(sm->PS[r * PSTRIDE + cA]);
                Af[mt][1] = __float_as_uint(sm->PS[(r + 8) * PSTRIDE + cA]);
                Af[mt][2] = __float_as_uint(sm->PS[r * PSTRIDE + cA + 4]);
                Af[mt][3] = __float_as_uint(sm->PS[(r + 8) * PSTRIDE + cA + 4]);
            }
#pragma unroll
            for (int nt = 0; nt < 8; nt++) {
                const int n = wn * 64 + nt * 8 + gid;
                unsigned B0 = __float_as_uint(sm->WhS[cur][(kk * 8 + tig) * WHSTRIDE + n]);
                unsigned B1 = __float_as_uint(sm->WhS[cur][(kk * 8 + tig + 4) * WHSTRIDE + n]);
                mma_tf32(acc[0][nt], Af[0], B0, B1);
                mma_tf32(acc[1][nt], Af[1], B0, B1);
            }
        }
    }

    // one-time row-sum reduction (warps own disjoint rows, both wn halves
    // computed identical sums -> duplicate write of same value is benign)
#pragma unroll
    for (int k = 0; k < 16; k++) {
        float s = rs[k];
#pragma unroll
        for (int o = 16; o; o >>= 1) s += __shfl_xor_sync(0xffffffffu, s, o);
        if (lane == 0) sm->lS[k * 8 + w] = s;
    }
    __syncthreads();
    if (t < 128) sm->invS[t] = (sm->lS[t] > 0.f) ? (1.0f / sm->lS[t]) : 0.f;
    __syncthreads();

    float* gout = out + ((size_t)b * NN + i0) * FO;
#pragma unroll
    for (int mt = 0; mt < 2; mt++) {
        const int r = wm * 32 + mt * 16 + gid;
        const float inv0 = sm->invS[r];
        const float inv1 = sm->invS[r + 8];
#pragma unroll
        for (int nt = 0; nt < 8; nt++) {
            const int cb = wn * 64 + nt * 8 + tig * 2;
            float2 v0 = {acc[mt][nt][0] * inv0, acc[mt][nt][1] * inv0};
            float2 v1 = {acc[mt][nt][2] * inv1, acc[mt][nt][3] * inv1};
            *(float2*)&gout[(size_t)r * FO + cb]       = v0;
            *(float2*)&gout[(size_t)(r + 8) * FO + cb] = v1;
        }
    }
}

// ---------------- launch ----------------
extern "C" void kernel_launch(void* const* d_in, const int* in_sizes, int n_in,
                              void* d_out, int out_size) {
    const float* h   = (const float*)d_in[0];
    const int*   adj = (const int*)d_in[1];
    const float* Ww  = (const float*)d_in[2];
    const float* Wb  = (const float*)d_in[3];
    const float* aw  = (const float*)d_in[4];
    const float* abp = (const float*)d_in[5];
    float* out = (float*)d_out;

    cudaFuncSetAttribute(k_main, cudaFuncAttributeMaxDynamicSharedMemorySize,
                         (int)sizeof(SmemMain));

    k_init<<<1, 32>>>();
    k_wh<<<BB * NN / 128, 256>>>(h, Ww, Wb);
    k_srcdst<<<BB * NN / 64, 256>>>(aw);
    k_main<<<dim3(NN / 128, BB), 256, sizeof(SmemMain)>>>(adj, abp, out);
}

// round 5
// speedup vs baseline: 2.1830x; 2.1830x over previous
#include <cuda_runtime.h>
#include <cuda_bf16.h>

// Problem constants
#define BB     4
#define NN     4096
#define FIN    256
#define FO     128
#define JT     32          // j-tile width in k_main
#define PSTRIDE 36         // PS row stride (conflict-free A-frag loads)
#define WHSTRIDE 136       // WhS row stride (conflict-free B-frag loads)

// Scratch (static device arrays: allocation-free rule)
__device__ float    g_Wh[BB * NN * FO];     // 8 MB
__device__ float    g_src[BB * NN];
__device__ float    g_dst[BB * NN];
__device__ unsigned g_dmax[BB];             // order-preserving encoded float max

// ---------------- order-preserving float<->uint encode ----------------
__device__ __forceinline__ unsigned encode_f(float f) {
    unsigned u = __float_as_uint(f);
    return (u & 0x80000000u) ? ~u : (u | 0x80000000u);
}
__device__ __forceinline__ float decode_key(unsigned k) {
    unsigned u = (k & 0x80000000u) ? (k ^ 0x80000000u) : ~k;
    return __uint_as_float(u);
}

// ---------------- kernel 0: init dmax ----------------
__global__ void k_init() {
    if (threadIdx.x < BB) g_dmax[threadIdx.x] = 0u;  // 0u <= every encoded key
}

// ---------------- kernel 1: Wh = h @ W^T + b (fp32 SGEMM) ----------------
__global__ __launch_bounds__(256, 1) void k_wh(const float* __restrict__ h,
                                               const float* __restrict__ Ww,
                                               const float* __restrict__ Wb) {
    __shared__ __align__(16) float As[16][132];   // [k][m]
    __shared__ __align__(16) float Bs[16][132];   // [k][n]
    const int t  = threadIdx.x;
    const int tx = t & 15;          // n dir
    const int ty = t >> 4;          // m dir
    const int m0 = blockIdx.x * 128;

    float acc[8][8];
#pragma unroll
    for (int i = 0; i < 8; i++)
#pragma unroll
        for (int j = 0; j < 8; j++) acc[i][j] = 0.f;

    for (int k0 = 0; k0 < FIN; k0 += 16) {
#pragma unroll
        for (int q = 0; q < 8; q++) {
            int idx = q * 256 + t;
            int row = idx >> 4, c = idx & 15;
            As[c][row] = h[(size_t)(m0 + row) * FIN + k0 + c];
        }
#pragma unroll
        for (int q = 0; q < 8; q++) {
            int idx = q * 256 + t;
            int n = idx >> 4, c = idx & 15;
            Bs[c][n] = Ww[n * FIN + k0 + c];
        }
        __syncthreads();
#pragma unroll
        for (int k = 0; k < 16; k++) {
            float4 a0 = *(const float4*)&As[k][ty * 8];
            float4 a1 = *(const float4*)&As[k][ty * 8 + 4];
            float4 b0 = *(const float4*)&Bs[k][tx * 8];
            float4 b1 = *(const float4*)&Bs[k][tx * 8 + 4];
            float a[8] = {a0.x, a0.y, a0.z, a0.w, a1.x, a1.y, a1.z, a1.w};
            float b[8] = {b0.x, b0.y, b0.z, b0.w, b1.x, b1.y, b1.z, b1.w};
#pragma unroll
            for (int i = 0; i < 8; i++)
#pragma unroll
                for (int j = 0; j < 8; j++) acc[i][j] = fmaf(a[i], b[j], acc[i][j]);
        }
        __syncthreads();
    }

    float wb[8];
#pragma unroll
    for (int j = 0; j < 8; j++) wb[j] = Wb[tx * 8 + j];
#pragma unroll
    for (int i = 0; i < 8; i++) {
        float* dst = &g_Wh[(size_t)(m0 + ty * 8 + i) * FO + tx * 8];
        float4 v0 = {acc[i][0] + wb[0], acc[i][1] + wb[1], acc[i][2] + wb[2], acc[i][3] + wb[3]};
        float4 v1 = {acc[i][4] + wb[4], acc[i][5] + wb[5], acc[i][6] + wb[6], acc[i][7] + wb[7]};
        *(float4*)dst       = v0;
        *(float4*)(dst + 4) = v1;
    }
}

// ---------------- kernel 2: src/dst dots + per-batch dst max ----------------
__global__ __launch_bounds__(256, 1) void k_srcdst(const float* __restrict__ aw) {
    const int t = threadIdx.x, w = t >> 5, lane = t & 31;
    const int mbase = blockIdx.x * 64 + w * 8;
    const int b = (blockIdx.x * 64) / NN;

    float as[4], ad[4];
#pragma unroll
    for (int q = 0; q < 4; q++) {
        as[q] = aw[lane + 32 * q];
        ad[q] = aw[FO + lane + 32 * q];
    }
    float dmax = -3.4e38f;
#pragma unroll
    for (int r = 0; r < 8; r++) {
        const int m = mbase + r;
        const float* row = &g_Wh[(size_t)m * FO];
        float s = 0.f, d = 0.f;
#pragma unroll
        for (int q = 0; q < 4; q++) {
            float v = row[lane + 32 * q];
            s = fmaf(v, as[q], s);
            d = fmaf(v, ad[q], d);
        }
#pragma unroll
        for (int o = 16; o; o >>= 1) {
            s += __shfl_xor_sync(0xffffffffu, s, o);
            d += __shfl_xor_sync(0xffffffffu, d, o);
        }
        if (lane == 0) { g_src[m] = s; g_dst[m] = d; }
        dmax = fmaxf(dmax, d);
    }
    if (lane == 0) atomicMax(&g_dmax[b], encode_f(dmax));
}

// ---------------- kernel 3: fused masked-softmax + PV (tf32 mma), 512 thr ----
struct __align__(16) SmemMain {
    float dstS[NN];                 // 16 KB
    float srcS[128];
    float mS[128];
    float lS[128];
    float invS[128];
    float WhS[2][JT * WHSTRIDE];    // 2 x 17 KB
    float PS[128 * PSTRIDE];        // 18 KB
};                                   // ~71.6 KB total -> 16 warps/SM

__device__ __forceinline__ void cpasync16(void* s, const void* g) {
    unsigned saddr = (unsigned)__cvta_generic_to_shared(s);
    asm volatile("cp.async.cg.shared.global [%0], [%1], 16;\n" :: "r"(saddr), "l"(g));
}

__device__ __forceinline__ void mma_tf32(float c[4], const unsigned a[4],
                                         unsigned b0, unsigned b1) {
    asm volatile(
        "mma.sync.aligned.m16n8k8.row.col.f32.tf32.tf32.f32 "
        "{%0,%1,%2,%3}, {%4,%5,%6,%7}, {%8,%9}, {%0,%1,%2,%3};\n"
        : "+f"(c[0]), "+f"(c[1]), "+f"(c[2]), "+f"(c[3])
        : "r"(a[0]), "r"(a[1]), "r"(a[2]), "r"(a[3]), "r"(b0), "r"(b1));
}

// stage one 32x128 Wh tile via cp.async (512 threads, 2 x 16B per thread)
__device__ __forceinline__ void issue_wh(SmemMain* sm, int buf,
                                         const float* __restrict__ whbase,
                                         int tile, int t) {
    const float* gwh = whbase + (size_t)tile * JT * FO;
#pragma unroll
    for (int q = 0; q < 2; q++) {
        int op = q * 512 + t;
        int row = op >> 5, seg = op & 31;         // 32 x 16B per 128-float row
        cpasync16(&sm->WhS[buf][row * WHSTRIDE + seg * 4],
                  gwh + row * FO + seg * 4);
    }
}

__global__ __launch_bounds__(512, 1) void k_main(const int* __restrict__ adj,
                                                 const float* __restrict__ abp,
                                                 float* __restrict__ out) {
    extern __shared__ char smraw[];
    SmemMain* sm = (SmemMain*)smraw;

    const int t = threadIdx.x;
    const int w = t >> 5, lane = t & 31;
    const int gid = lane >> 2, tig = lane & 3;
    const int wm = w & 3;      // 4 m-blocks of 32 rows
    const int wn = w >> 2;     // 4 n-blocks of 32 cols
    const int b  = blockIdx.y;
    const int i0 = blockIdx.x * 128;
    const float ab = __ldg(abp);

    const int*   adjbase = adj + ((size_t)b * NN + i0) * NN;
    const float* whbase  = g_Wh + (size_t)b * NN * FO;
    // phase-1 row ownership: rows k*16 + w, k = 0..7
    const int* aptr = adjbase + (size_t)w * NN + lane;

    // prefetch Wh tile 0 + adj tile 0 (registers)
    issue_wh(sm, 0, whbase, 0, t);
    asm volatile("cp.async.commit_group;\n" ::: "memory");
    int adjn[8];
#pragma unroll
    for (int k = 0; k < 8; k++)
        adjn[k] = __ldcs(aptr + (size_t)k * 16 * NN);

    // prologue SMEM fills
    const float dmaxf = decode_key(g_dmax[b]);
#pragma unroll
    for (int q = 0; q < 8; q++)
        sm->dstS[q * 512 + t] = g_dst[(size_t)b * NN + q * 512 + t];
    if (t < 128) {
        float s = g_src[(size_t)b * NN + i0 + t] + ab;
        sm->srcS[t] = s;
        float e = s + dmaxf;
        sm->mS[t] = fmaxf(e, 0.01f * e);   // leaky of the per-row upper bound
    }
    __syncthreads();

    float src_r[8], m_r[8], rs[8];
#pragma unroll
    for (int k = 0; k < 8; k++) {
        src_r[k] = sm->srcS[k * 16 + w];
        m_r[k]   = sm->mS[k * 16 + w];
        rs[k]    = 0.f;
    }

    float acc[2][4][4];
#pragma unroll
    for (int mt = 0; mt < 2; mt++)
#pragma unroll
        for (int nt = 0; nt < 4; nt++)
#pragma unroll
            for (int c = 0; c < 4; c++) acc[mt][nt][c] = 0.f;

    const int NTILES = NN / JT;   // 128
    for (int tile = 0; tile < NTILES; tile++) {
        const int cur = tile & 1;
        asm volatile("cp.async.wait_group 0;\n" ::: "memory");
        __syncthreads();          // WhS[cur] ready; WhS[cur^1] + PS free

        // rotate adj regs; prefetch next tile's adj + Wh immediately
        int adjc[8];
#pragma unroll
        for (int k = 0; k < 8; k++) adjc[k] = adjn[k];
        if (tile + 1 < NTILES) {
            const int* ap = aptr + (size_t)(tile + 1) * JT;
#pragma unroll
            for (int k = 0; k < 8; k++)
                adjn[k] = __ldcs(ap + (size_t)k * 16 * NN);
            issue_wh(sm, cur ^ 1, whbase, tile + 1, t);
            asm volatile("cp.async.commit_group;\n" ::: "memory");
        }

        // ---- phase 1: P tile (row sums stay in registers) ----
        const float dval = sm->dstS[tile * JT + lane];
#pragma unroll
        for (int k = 0; k < 8; k++) {
            float e = src_r[k] + dval;
            e = fmaxf(e, 0.01f * e);            // LeakyReLU
            float p = (adjc[k] > 0) ? __expf(e - m_r[k]) : 0.f;
            sm->PS[(k * 16 + w) * PSTRIDE + lane] = p;
            rs[k] += p;
        }
        __syncthreads();          // PS ready

        // ---- phase 2: acc += P(tf32) @ Wh(tf32) ----
#pragma unroll
        for (int kk = 0; kk < 4; kk++) {
            unsigned Af[2][4];
#pragma unroll
            for (int mt = 0; mt < 2; mt++) {
                const int r  = wm * 32 + mt * 16 + gid;
                const int cA = kk * 8 + tig;
                Af[mt][0] = __float_as_uint(sm->PS[r * PSTRIDE + cA]);
                Af[mt][1] = __float_as_uint(sm->PS[(r + 8) * PSTRIDE + cA]);
                Af[mt][2] = __float_as_uint(sm->PS[r * PSTRIDE + cA + 4]);
                Af[mt][3] = __float_as_uint(sm->PS[(r + 8) * PSTRIDE + cA + 4]);
            }
#pragma unroll
            for (int nt = 0; nt < 4; nt++) {
                const int n = wn * 32 + nt * 8 + gid;
                unsigned B0 = __float_as_uint(sm->WhS[cur][(kk * 8 + tig) * WHSTRIDE + n]);
                unsigned B1 = __float_as_uint(sm->WhS[cur][(kk * 8 + tig + 4) * WHSTRIDE + n]);
                mma_tf32(acc[0][nt], Af[0], B0, B1);
                mma_tf32(acc[1][nt], Af[1], B0, B1);
            }
        }
    }

    // one-time row-sum reduction; warp w owns rows k*16+w (unique writers)
#pragma unroll
    for (int k = 0; k < 8; k++) {
        float s = rs[k];
#pragma unroll
        for (int o = 16; o; o >>= 1) s += __shfl_xor_sync(0xffffffffu, s, o);
        if (lane == 0) sm->lS[k * 16 + w] = s;
    }
    __syncthreads();
    if (t < 128) sm->invS[t] = (sm->lS[t] > 0.f) ? (1.0f / sm->lS[t]) : 0.f;
    __syncthreads();

    float* gout = out + ((size_t)b * NN + i0) * FO;
#pragma unroll
    for (int mt = 0; mt < 2; mt++) {
        const int r = wm * 32 + mt * 16 + gid;
        const float inv0 = sm->invS[r];
        const float inv1 = sm->invS[r + 8];
#pragma unroll
        for (int nt = 0; nt < 4; nt++) {
            const int cb = wn * 32 + nt * 8 + tig * 2;
            float2 v0 = {acc[mt][nt][0] * inv0, acc[mt][nt][1] * inv0};
            float2 v1 = {acc[mt][nt][2] * inv1, acc[mt][nt][3] * inv1};
            *(float2*)&gout[(size_t)r * FO + cb]       = v0;
            *(float2*)&gout[(size_t)(r + 8) * FO + cb] = v1;
        }
    }
}

// ---------------- launch ----------------
extern "C" void kernel_launch(void* const* d_in, const int* in_sizes, int n_in,
                              void* d_out, int out_size) {
    const float* h   = (const float*)d_in[0];
    const int*   adj = (const int*)d_in[1];
    const float* Ww  = (const float*)d_in[2];
    const float* Wb  = (const float*)d_in[3];
    const float* aw  = (const float*)d_in[4];
    const float* abp = (const float*)d_in[5];
    float* out = (float*)d_out;

    cudaFuncSetAttribute(k_main, cudaFuncAttributeMaxDynamicSharedMemorySize,
                         (int)sizeof(SmemMain));

    k_init<<<1, 32>>>();
    k_wh<<<BB * NN / 128, 256>>>(h, Ww, Wb);
    k_srcdst<<<BB * NN / 64, 256>>>(aw);
    k_main<<<dim3(NN / 128, BB), 512, sizeof(SmemMain)>>>(adj, abp, out);
}

// round 17
// speedup vs baseline: 2.3235x; 1.0643x over previous
#include <cuda_runtime.h>
#include <cuda_bf16.h>

// Problem constants
#define BB     4
#define NN     4096
#define FIN    256
#define FO     128
#define JT     32          // j-tile width in k_main
#define IT     64          // i-tile height in k_main (64 rows -> 2 CTAs/SM)
#define PSTRIDE 36         // PS row stride (conflict-free A-frag loads)
#define WHSTRIDE 136       // WhS row stride (conflict-free B-frag loads)

// Scratch (static device arrays: allocation-free rule)
__device__ float    g_Wh[BB * NN * FO];     // 8 MB
__device__ float    g_src[BB * NN];
__device__ float    g_dst[BB * NN];
__device__ unsigned g_dmax[BB];             // order-preserving encoded float max

// ---------------- order-preserving float<->uint encode ----------------
__device__ __forceinline__ unsigned encode_f(float f) {
    unsigned u = __float_as_uint(f);
    return (u & 0x80000000u) ? ~u : (u | 0x80000000u);
}
__device__ __forceinline__ float decode_key(unsigned k) {
    unsigned u = (k & 0x80000000u) ? (k ^ 0x80000000u) : ~k;
    return __uint_as_float(u);
}

// ---------------- kernel 0: init dmax ----------------
__global__ void k_init() {
    if (threadIdx.x < BB) g_dmax[threadIdx.x] = 0u;  // 0u <= every encoded key
}

// ---------------- kernel 1: Wh = h @ W^T + b, fused src/dst/dmax epilogue ----
// M=16384, N=128, K=256. BM=128, BN=128, BK=16. 256 threads, 8x8 per thread.
__global__ __launch_bounds__(256, 1) void k_wh(const float* __restrict__ h,
                                               const float* __restrict__ Ww,
                                               const float* __restrict__ Wb,
                                               const float* __restrict__ aw) {
    __shared__ __align__(16) float As[16][132];   // [k][m]
    __shared__ __align__(16) float Bs[16][132];   // [k][n]
    const int t  = threadIdx.x;
    const int tx = t & 15;          // n dir
    const int ty = t >> 4;          // m dir
    const int m0 = blockIdx.x * 128;

    float acc[8][8];
#pragma unroll
    for (int i = 0; i < 8; i++)
#pragma unroll
        for (int j = 0; j < 8; j++) acc[i][j] = 0.f;

    for (int k0 = 0; k0 < FIN; k0 += 16) {
#pragma unroll
        for (int q = 0; q < 8; q++) {
            int idx = q * 256 + t;
            int row = idx >> 4, c = idx & 15;
            As[c][row] = h[(size_t)(m0 + row) * FIN + k0 + c];
        }
#pragma unroll
        for (int q = 0; q < 8; q++) {
            int idx = q * 256 + t;
            int n = idx >> 4, c = idx & 15;
            Bs[c][n] = Ww[n * FIN + k0 + c];
        }
        __syncthreads();
#pragma unroll
        for (int k = 0; k < 16; k++) {
            float4 a0 = *(const float4*)&As[k][ty * 8];
            float4 a1 = *(const float4*)&As[k][ty * 8 + 4];
            float4 b0 = *(const float4*)&Bs[k][tx * 8];
            float4 b1 = *(const float4*)&Bs[k][tx * 8 + 4];
            float a[8] = {a0.x, a0.y, a0.z, a0.w, a1.x, a1.y, a1.z, a1.w};
            float b[8] = {b0.x, b0.y, b0.z, b0.w, b1.x, b1.y, b1.z, b1.w};
#pragma unroll
            for (int i = 0; i < 8; i++)
#pragma unroll
                for (int j = 0; j < 8; j++) acc[i][j] = fmaf(a[i], b[j], acc[i][j]);
        }
        __syncthreads();
    }

    float wb[8], as8[8], ad8[8];
#pragma unroll
    for (int j = 0; j < 8; j++) {
        wb[j]  = Wb[tx * 8 + j];
        as8[j] = aw[tx * 8 + j];
        ad8[j] = aw[FO + tx * 8 + j];
    }
    float dmax = -3.4e38f;
#pragma unroll
    for (int i = 0; i < 8; i++) {
        const int m = m0 + ty * 8 + i;
        float v[8];
#pragma unroll
        for (int j = 0; j < 8; j++) v[j] = acc[i][j] + wb[j];
        // store Wh row slice
        float* dst = &g_Wh[(size_t)m * FO + tx * 8];
        *(float4*)dst       = make_float4(v[0], v[1], v[2], v[3]);
        *(float4*)(dst + 4) = make_float4(v[4], v[5], v[6], v[7]);
        // fused src/dst dots: partial over this thread's 8 cols,
        // reduce across the 16-lane tx segment (xor 8/4/2/1 stays in-half)
        float s = 0.f, d = 0.f;
#pragma unroll
        for (int j = 0; j < 8; j++) {
            s = fmaf(v[j], as8[j], s);
            d = fmaf(v[j], ad8[j], d);
        }
#pragma unroll
        for (int o = 8; o; o >>= 1) {
            s += __shfl_xor_sync(0xffffffffu, s, o);
            d += __shfl_xor_sync(0xffffffffu, d, o);
        }
        if (tx == 0) {
            g_src[m] = s;
            g_dst[m] = d;
            dmax = fmaxf(dmax, d);
        }
    }
    if (tx == 0) atomicMax(&g_dmax[m0 / NN], encode_f(dmax));
}

// ---------------- kernel 3: fused masked-softmax + PV (tf32 mma) ----------
// 64-row i-tiles, 256 threads (8 warps), 2 CTAs/SM -> decoupled barriers.
struct __align__(16) SmemMain {
    float dstS[NN];                 // 16 KB
    float srcS[IT];
    float mS[IT];
    float lS[IT];
    float invS[IT];
    float WhS[2][JT * WHSTRIDE];    // 2 x 17 KB
    float PS[IT * PSTRIDE];         // 9.2 KB
};                                   // ~60.3 KB -> 2 CTAs/SM

__device__ __forceinline__ void cpasync16(void* s, const void* g) {
    unsigned saddr = (unsigned)__cvta_generic_to_shared(s);
    asm volatile("cp.async.cg.shared.global [%0], [%1], 16;\n" :: "r"(saddr), "l"(g));
}

__device__ __forceinline__ void mma_tf32(float c[4], const unsigned a[4],
                                         unsigned b0, unsigned b1) {
    asm volatile(
        "mma.sync.aligned.m16n8k8.row.col.f32.tf32.tf32.f32 "
        "{%0,%1,%2,%3}, {%4,%5,%6,%7}, {%8,%9}, {%0,%1,%2,%3};\n"
        : "+f"(c[0]), "+f"(c[1]), "+f"(c[2]), "+f"(c[3])
        : "r"(a[0]), "r"(a[1]), "r"(a[2]), "r"(a[3]), "r"(b0), "r"(b1));
}

// stage one 32x128 Wh tile via cp.async (256 threads, 4 x 16B per thread)
__device__ __forceinline__ void issue_wh(SmemMain* sm, int buf,
                                         const float* __restrict__ whbase,
                                         int tile, int t) {
    const float* gwh = whbase + (size_t)tile * JT * FO;
#pragma unroll
    for (int q = 0; q < 4; q++) {
        int op = q * 256 + t;
        int row = op >> 5, seg = op & 31;         // 32 x 16B per 128-float row
        cpasync16(&sm->WhS[buf][row * WHSTRIDE + seg * 4],
                  gwh + row * FO + seg * 4);
    }
}

__global__ __launch_bounds__(256, 2) void k_main(const int* __restrict__ adj,
                                                 const float* __restrict__ abp,
                                                 float* __restrict__ out) {
    extern __shared__ char smraw[];
    SmemMain* sm = (SmemMain*)smraw;

    const int t = threadIdx.x;
    const int w = t >> 5, lane = t & 31;
    const int gid = lane >> 2, tig = lane & 3;
    const int wm = w & 1;      // 2 m-blocks of 32 rows
    const int wn = w >> 1;     // 4 n-blocks of 32 cols
    const int b  = blockIdx.y;
    const int i0 = blockIdx.x * IT;
    const float ab = __ldg(abp);

    const int*   adjbase = adj + ((size_t)b * NN + i0) * NN;
    const float* whbase  = g_Wh + (size_t)b * NN * FO;
    // phase-1 row ownership: rows k*8 + w, k = 0..7
    const int* aptr = adjbase + (size_t)w * NN + lane;

    // prefetch Wh tile 0 + adj tile 0 (registers)
    issue_wh(sm, 0, whbase, 0, t);
    asm volatile("cp.async.commit_group;\n" ::: "memory");
    int adjn[8];
#pragma unroll
    for (int k = 0; k < 8; k++)
        adjn[k] = __ldcs(aptr + (size_t)k * 8 * NN);

    // prologue SMEM fills
    const float dmaxf = decode_key(g_dmax[b]);
#pragma unroll
    for (int q = 0; q < 16; q++)
        sm->dstS[q * 256 + t] = g_dst[(size_t)b * NN + q * 256 + t];
    if (t < IT) {
        float s = g_src[(size_t)b * NN + i0 + t] + ab;
        sm->srcS[t] = s;
        float e = s + dmaxf;
        sm->mS[t] = fmaxf(e, 0.01f * e);   // leaky of the per-row upper bound
    }
    __syncthreads();

    float src_r[8], m_r[8], rs[8];
#pragma unroll
    for (int k = 0; k < 8; k++) {
        src_r[k] = sm->srcS[k * 8 + w];
        m_r[k]   = sm->mS[k * 8 + w];
        rs[k]    = 0.f;
    }

    float acc[2][4][4];
#pragma unroll
    for (int mt = 0; mt < 2; mt++)
#pragma unroll
        for (int nt = 0; nt < 4; nt++)
#pragma unroll
            for (int c = 0; c < 4; c++) acc[mt][nt][c] = 0.f;

    const int NTILES = NN / JT;   // 128
    for (int tile = 0; tile < NTILES; tile++) {
        const int cur = tile & 1;
        asm volatile("cp.async.wait_group 0;\n" ::: "memory");
        __syncthreads();          // WhS[cur] ready; WhS[cur^1] + PS free

        // rotate adj regs; prefetch next tile's adj + Wh immediately
        int adjc[8];
#pragma unroll
        for (int k = 0; k < 8; k++) adjc[k] = adjn[k];
        if (tile + 1 < NTILES) {
            const int* ap = aptr + (size_t)(tile + 1) * JT;
#pragma unroll
            for (int k = 0; k < 8; k++)
                adjn[k] = __ldcs(ap + (size_t)k * 8 * NN);
            issue_wh(sm, cur ^ 1, whbase, tile + 1, t);
            asm volatile("cp.async.commit_group;\n" ::: "memory");
        }

        // ---- phase 1: P tile (row sums stay in registers) ----
        const float dval = sm->dstS[tile * JT + lane];
#pragma unroll
        for (int k = 0; k < 8; k++) {
            float e = src_r[k] + dval;
            e = fmaxf(e, 0.01f * e);            // LeakyReLU
            float p = (adjc[k] > 0) ? __expf(e - m_r[k]) : 0.f;
            sm->PS[(k * 8 + w) * PSTRIDE + lane] = p;
            rs[k] += p;
        }
        __syncthreads();          // PS ready

        // ---- phase 2: acc += P(tf32) @ Wh(tf32) ----
#pragma unroll
        for (int kk = 0; kk < 4; kk++) {
            unsigned Af[2][4];
#pragma unroll
            for (int mt = 0; mt < 2; mt++) {
                const int r  = wm * 32 + mt * 16 + gid;
                const int cA = kk * 8 + tig;
                Af[mt][0] = __float_as_uint(sm->PS[r * PSTRIDE + cA]);
                Af[mt][1] = __float_as_uint(sm->PS[(r + 8) * PSTRIDE + cA]);
                Af[mt][2] = __float_as_uint(sm->PS[r * PSTRIDE + cA + 4]);
                Af[mt][3] = __float_as_uint(sm->PS[(r + 8) * PSTRIDE + cA + 4]);
            }
#pragma unroll
            for (int nt = 0; nt < 4; nt++) {
                const int n = wn * 32 + nt * 8 + gid;
                unsigned B0 = __float_as_uint(sm->WhS[cur][(kk * 8 + tig) * WHSTRIDE + n]);
                unsigned B1 = __float_as_uint(sm->WhS[cur][(kk * 8 + tig + 4) * WHSTRIDE + n]);
                mma_tf32(acc[0][nt], Af[0], B0, B1);
                mma_tf32(acc[1][nt], Af[1], B0, B1);
            }
        }
    }

    // one-time row-sum reduction; warp w owns rows k*8+w (unique writers)
#pragma unroll
    for (int k = 0; k < 8; k++) {
        float s = rs[k];
#pragma unroll
        for (int o = 16; o; o >>= 1) s += __shfl_xor_sync(0xffffffffu, s, o);
        if (lane == 0) sm->lS[k * 8 + w] = s;
    }
    __syncthreads();
    if (t < IT) sm->invS[t] = (sm->lS[t] > 0.f) ? (1.0f / sm->lS[t]) : 0.f;
    __syncthreads();

    float* gout = out + ((size_t)b * NN + i0) * FO;
#pragma unroll
    for (int mt = 0; mt < 2; mt++) {
        const int r = wm * 32 + mt * 16 + gid;
        const float inv0 = sm->invS[r];
        const float inv1 = sm->invS[r + 8];
#pragma unroll
        for (int nt = 0; nt < 4; nt++) {
            const int cb = wn * 32 + nt * 8 + tig * 2;
            float2 v0 = {acc[mt][nt][0] * inv0, acc[mt][nt][1] * inv0};
            float2 v1 = {acc[mt][nt][2] * inv1, acc[mt][nt][3] * inv1};
            *(float2*)&gout[(size_t)r * FO + cb]       = v0;
            *(float2*)&gout[(size_t)(r + 8) * FO + cb] = v1;
        }
    }
}

// ---------------- launch ----------------
extern "C" void kernel_launch(void* const* d_in, const int* in_sizes, int n_in,
                              void* d_out, int out_size) {
    const float* h   = (const float*)d_in[0];
    const int*   adj = (const int*)d_in[1];
    const float* Ww  = (const float*)d_in[2];
    const float* Wb  = (const float*)d_in[3];
    const float* aw  = (const float*)d_in[4];
    const float* abp = (const float*)d_in[5];
    float* out = (float*)d_out;

    cudaFuncSetAttribute(k_main, cudaFuncAttributeMaxDynamicSharedMemorySize,
                         (int)sizeof(SmemMain));

    k_init<<<1, 32>>>();
    k_wh<<<BB * NN / 128, 256>>>(h, Ww, Wb, aw);
    k_main<<<dim3(NN / IT, BB), 256, sizeof(SmemMain)>>>(adj, abp, out);
}